// round 1
// baseline (speedup 1.0000x reference)
#include <cuda_runtime.h>
#include <cuda_bf16.h>
#include <cstdint>

// Problem dims (fixed by the reference)
#define BB 2
#define TT 2048
#define DD 1024
#define NN 16
#define DCONV 4
#define MROWS (BB*TT)          // 4096
#define E2 (2*DD)              // 2048
#define NPAR (2*NN+1)          // 33

// ---------- scratch (static device allocations only) ----------
__device__ float g_xz[(size_t)MROWS * E2];       // in_proj output (x_in | z)
__device__ float g_xconv[(size_t)MROWS * DD];    // conv+silu output
__device__ float g_params[(size_t)MROWS * NPAR]; // x_proj output (B,C,dt_raw)
__device__ float g_y[(size_t)MROWS * DD];        // scan output * silu(z)

// =====================================================================
// GEMM: C[M,N] = A[M,K] @ W[N,K]^T   (both row-major, K contiguous)
// 128x128 tile, BK=8, 256 threads, 8x8 per thread
// =====================================================================
__global__ __launch_bounds__(256) void gemm_nt_kernel(
    const float* __restrict__ A, const float* __restrict__ W,
    float* __restrict__ C, int M, int N, int K)
{
    __shared__ float As[8][128];
    __shared__ float Ws[8][128];

    const int tid = threadIdx.x;
    const int blockRow = blockIdx.y * 128;
    const int blockCol = blockIdx.x * 128;
    const int ty = tid >> 4;        // 0..15
    const int tx = tid & 15;        // 0..15

    const int lr = tid >> 1;        // 0..127 (row within tile)
    const int lk = (tid & 1) * 4;   // 0 or 4

    const float* Aptr = A + (size_t)(blockRow + lr) * K + lk;
    const float* Wptr = W + (size_t)(blockCol + lr) * K + lk;

    float acc[8][8];
    #pragma unroll
    for (int i = 0; i < 8; i++)
        #pragma unroll
        for (int j = 0; j < 8; j++) acc[i][j] = 0.f;

    for (int k0 = 0; k0 < K; k0 += 8) {
        float4 a4 = *(const float4*)(Aptr + k0);
        float4 w4 = *(const float4*)(Wptr + k0);
        __syncthreads();
        As[lk + 0][lr] = a4.x; As[lk + 1][lr] = a4.y;
        As[lk + 2][lr] = a4.z; As[lk + 3][lr] = a4.w;
        Ws[lk + 0][lr] = w4.x; Ws[lk + 1][lr] = w4.y;
        Ws[lk + 2][lr] = w4.z; Ws[lk + 3][lr] = w4.w;
        __syncthreads();
        #pragma unroll
        for (int k = 0; k < 8; k++) {
            float ra[8], rb[8];
            *(float4*)&ra[0] = *(const float4*)&As[k][ty * 8];
            *(float4*)&ra[4] = *(const float4*)&As[k][ty * 8 + 4];
            *(float4*)&rb[0] = *(const float4*)&Ws[k][tx * 8];
            *(float4*)&rb[4] = *(const float4*)&Ws[k][tx * 8 + 4];
            #pragma unroll
            for (int i = 0; i < 8; i++)
                #pragma unroll
                for (int j = 0; j < 8; j++)
                    acc[i][j] = fmaf(ra[i], rb[j], acc[i][j]);
        }
    }

    #pragma unroll
    for (int i = 0; i < 8; i++) {
        float* crow = C + (size_t)(blockRow + ty * 8 + i) * N + blockCol + tx * 8;
        *(float4*)(crow)     = make_float4(acc[i][0], acc[i][1], acc[i][2], acc[i][3]);
        *(float4*)(crow + 4) = make_float4(acc[i][4], acc[i][5], acc[i][6], acc[i][7]);
    }
}

// =====================================================================
// Depthwise causal conv (width 4) + bias + SiLU
// x_in = g_xz[..., 0:D]; out -> g_xconv
// =====================================================================
__global__ void conv_silu_kernel(const float* __restrict__ xz,
                                 const float* __restrict__ cw,
                                 const float* __restrict__ cb,
                                 float* __restrict__ xconv)
{
    int idx = blockIdx.x * blockDim.x + threadIdx.x;   // 0 .. B*T*D-1
    if (idx >= MROWS * DD) return;
    int d  = idx & (DD - 1);
    int bt = idx >> 10;              // b*T + t
    int t  = bt & (TT - 1);
    int b  = bt >> 11;

    float acc = cb[d];
    #pragma unroll
    for (int j = 0; j < DCONV; j++) {
        int tt = t - (DCONV - 1) + j;
        if (tt >= 0)
            acc = fmaf(xz[(size_t)(b * TT + tt) * E2 + d], cw[d * DCONV + j], acc);
    }
    // SiLU
    float s = acc / (1.0f + __expf(-acc));
    xconv[(size_t)bt * DD + d] = s;
}

// =====================================================================
// x_proj: params[row, e] = sum_k xconv[row,k] * W[e,k]   (33 outputs/row)
// one block per row
// =====================================================================
__global__ __launch_bounds__(64) void xproj_kernel(const float* __restrict__ xconv,
                                                   const float* __restrict__ W,
                                                   float* __restrict__ params)
{
    __shared__ float sx[DD];
    int row = blockIdx.x;
    const float4* xr = (const float4*)(xconv + (size_t)row * DD);
    for (int i = threadIdx.x; i < DD / 4; i += 64)
        ((float4*)sx)[i] = xr[i];
    __syncthreads();

    int e = threadIdx.x;
    if (e < NPAR) {
        const float* w = W + (size_t)e * DD;
        float acc0 = 0.f, acc1 = 0.f, acc2 = 0.f, acc3 = 0.f;
        #pragma unroll 4
        for (int k = 0; k < DD; k += 4) {
            float4 w4 = *(const float4*)(w + k);
            acc0 = fmaf(sx[k + 0], w4.x, acc0);
            acc1 = fmaf(sx[k + 1], w4.y, acc1);
            acc2 = fmaf(sx[k + 2], w4.z, acc2);
            acc3 = fmaf(sx[k + 3], w4.w, acc3);
        }
        params[(size_t)row * NPAR + e] = (acc0 + acc1) + (acc2 + acc3);
    }
}

// =====================================================================
// Selective scan: per (b,d) channel, sequential over T.
// h[n]_{t} = exp(dt*A[d,n]) * h[n]_{t-1} + dt*B[t,n]*x_conv[t,d]
// y[t,d] = (sum_n h[n]*C[t,n]) * silu(z[t,d])
// grid: B * (D/32) blocks of 32 threads
// =====================================================================
__global__ __launch_bounds__(32) void scan_kernel(const float* __restrict__ params,
                                                  const float* __restrict__ xconv,
                                                  const float* __restrict__ xz,
                                                  const float* __restrict__ dtw,
                                                  const float* __restrict__ dtb,
                                                  const float* __restrict__ A_log,
                                                  float* __restrict__ y)
{
    const int b = blockIdx.x / (DD / 32);
    const int d = (blockIdx.x % (DD / 32)) * 32 + threadIdx.x;

    float a[NN];
    #pragma unroll
    for (int n = 0; n < NN; n++)
        a[n] = -expf(A_log[(size_t)d * NN + n]);

    const float w    = dtw[d];
    const float bias = dtb[d];

    float h[NN];
    #pragma unroll
    for (int n = 0; n < NN; n++) h[n] = 0.f;

    const size_t rowbase = (size_t)b * TT;
    for (int t = 0; t < TT; t++) {
        const size_t r = rowbase + t;
        const float* p = params + r * NPAR;
        float s = p[32];
        float v = fmaf(s, w, bias);
        float dt = (v > 20.f) ? v : log1pf(__expf(v));
        float xv = xconv[r * DD + d];
        float zv = xz[r * E2 + DD + d];
        float dtx = dt * xv;
        float yv = 0.f;
        #pragma unroll
        for (int n = 0; n < NN; n++) {
            float dA = __expf(dt * a[n]);
            h[n] = fmaf(dA, h[n], dtx * p[n]);
            yv = fmaf(h[n], p[NN + n], yv);
        }
        float sil = zv / (1.0f + __expf(-zv));
        y[r * DD + d] = yv * sil;
    }
}

// =====================================================================
// launch
// =====================================================================
extern "C" void kernel_launch(void* const* d_in, const int* in_sizes, int n_in,
                              void* d_out, int out_size)
{
    const float* x         = (const float*)d_in[0];
    const float* in_proj_w = (const float*)d_in[1];
    const float* conv_w    = (const float*)d_in[2];
    const float* conv_b    = (const float*)d_in[3];
    const float* x_proj_w  = (const float*)d_in[4];
    const float* dt_proj_w = (const float*)d_in[5];
    const float* dt_proj_b = (const float*)d_in[6];
    const float* A_log     = (const float*)d_in[7];
    const float* out_proj_w= (const float*)d_in[8];
    float* out = (float*)d_out;

    float *xz, *xconv, *params, *yb;
    cudaGetSymbolAddress((void**)&xz,     g_xz);
    cudaGetSymbolAddress((void**)&xconv,  g_xconv);
    cudaGetSymbolAddress((void**)&params, g_params);
    cudaGetSymbolAddress((void**)&yb,     g_y);

    // 1) in_proj: (4096,1024) @ (2048,1024)^T -> (4096,2048)
    {
        dim3 grid(E2 / 128, MROWS / 128);
        gemm_nt_kernel<<<grid, 256>>>(x, in_proj_w, xz, MROWS, E2, DD);
    }
    // 2) depthwise conv + SiLU
    {
        int total = MROWS * DD;
        conv_silu_kernel<<<(total + 255) / 256, 256>>>(xz, conv_w, conv_b, xconv);
    }
    // 3) x_proj: (4096,1024) @ (33,1024)^T -> (4096,33)
    xproj_kernel<<<MROWS, 64>>>(xconv, x_proj_w, params);
    // 4) selective scan (+ gate by silu(z))
    scan_kernel<<<BB * (DD / 32), 32>>>(params, xconv, xz, dt_proj_w, dt_proj_b, A_log, yb);
    // 5) out_proj: (4096,1024) @ (1024,1024)^T -> (4096,1024)
    {
        dim3 grid(DD / 128, MROWS / 128);
        gemm_nt_kernel<<<grid, 256>>>(yb, out_proj_w, out, MROWS, DD, DD);
    }
}

// round 2
// speedup vs baseline: 2.0037x; 2.0037x over previous
#include <cuda_runtime.h>
#include <cuda_bf16.h>
#include <cstdint>

// Problem dims (fixed by the reference)
#define BB 2
#define TT 2048
#define DD 1024
#define NN 16
#define DCONV 4
#define MROWS (BB*TT)          // 4096
#define E2 (2*DD)              // 2048
#define NPAR (2*NN+1)          // 33

// ---------- scratch (static device allocations only) ----------
__device__ float g_xz[(size_t)MROWS * E2];       // in_proj output (x_in | z)
__device__ float g_xconv[(size_t)MROWS * DD];    // conv+silu output
__device__ float g_params[(size_t)MROWS * NPAR]; // x_proj output (B,C,dt_raw)
__device__ float g_y[(size_t)MROWS * DD];        // scan output * silu(z)

// =====================================================================
// Tensor-core GEMM with bf16 3-term split (fp32-accurate):
//   C[M,N] = A[M,K] @ W[N,K]^T
//   A = Ahi + Alo (bf16), W = Whi + Wlo (bf16)
//   C ≈ Ahi*Whi + Ahi*Wlo + Alo*Whi   (lo*lo term ~2^-18, dropped)
// Block tile 128x128, BK=32, 256 threads (8 warps), warp tile 64x32.
// =====================================================================
#define GLDA 40  // smem row stride in bf16 (32 + 8 pad) = 80B, conflict-free for ldmatrix

__device__ __forceinline__ void mma16816(float* c, const uint32_t* a, const uint32_t* b) {
    asm volatile(
        "mma.sync.aligned.m16n8k16.row.col.f32.bf16.bf16.f32 "
        "{%0,%1,%2,%3}, {%4,%5,%6,%7}, {%8,%9}, {%0,%1,%2,%3};"
        : "+f"(c[0]), "+f"(c[1]), "+f"(c[2]), "+f"(c[3])
        : "r"(a[0]), "r"(a[1]), "r"(a[2]), "r"(a[3]), "r"(b[0]), "r"(b[1]));
}

__device__ __forceinline__ void ldm4(uint32_t* r, uint32_t addr) {
    asm volatile(
        "ldmatrix.sync.aligned.m8n8.x4.shared.b16 {%0,%1,%2,%3}, [%4];"
        : "=r"(r[0]), "=r"(r[1]), "=r"(r[2]), "=r"(r[3]) : "r"(addr));
}

__global__ __launch_bounds__(256) void gemm_tc_split(
    const float* __restrict__ A, const float* __restrict__ W,
    float* __restrict__ C, int M, int N, int K)
{
    __shared__ __align__(16) __nv_bfloat16 sAhi[128][GLDA];
    __shared__ __align__(16) __nv_bfloat16 sAlo[128][GLDA];
    __shared__ __align__(16) __nv_bfloat16 sWhi[128][GLDA];
    __shared__ __align__(16) __nv_bfloat16 sWlo[128][GLDA];

    const int tid  = threadIdx.x;
    const int lane = tid & 31;
    const int warp = tid >> 5;
    const int wm   = warp >> 2;          // 0..1 -> 64 rows each
    const int wn   = warp & 3;           // 0..3 -> 32 cols each
    const int brow = blockIdx.y * 128;
    const int bcol = blockIdx.x * 128;

    float acc[4][4][4];
    #pragma unroll
    for (int i = 0; i < 4; i++)
        #pragma unroll
        for (int j = 0; j < 4; j++)
            #pragma unroll
            for (int k = 0; k < 4; k++) acc[i][j][k] = 0.f;

    // ldmatrix base addresses (byte offsets within smem)
    const uint32_t bAhi = (uint32_t)__cvta_generic_to_shared(&sAhi[0][0]);
    const uint32_t bAlo = (uint32_t)__cvta_generic_to_shared(&sAlo[0][0]);
    const uint32_t bWhi = (uint32_t)__cvta_generic_to_shared(&sWhi[0][0]);
    const uint32_t bWlo = (uint32_t)__cvta_generic_to_shared(&sWlo[0][0]);

    // A fragment addressing: row = wm*64 + mi*16 + (lane&15); koff = (lane>>4)*8
    uint32_t offA[4];
    #pragma unroll
    for (int mi = 0; mi < 4; mi++) {
        int row = wm * 64 + mi * 16 + (lane & 15);
        int ko  = (lane >> 4) * 8;
        offA[mi] = (uint32_t)(row * GLDA + ko) * 2u;
    }
    // B fragment addressing (x4 covers 16 n-cols = 2 nfrags):
    // nrow = wn*32 + ni2*16 + (lane&7) + ((lane>>4)<<3); koff = ((lane>>3)&1)*8
    uint32_t offB[2];
    #pragma unroll
    for (int ni2 = 0; ni2 < 2; ni2++) {
        int row = wn * 32 + ni2 * 16 + (lane & 7) + ((lane >> 4) << 3);
        int ko  = ((lane >> 3) & 1) * 8;
        offB[ni2] = (uint32_t)(row * GLDA + ko) * 2u;
    }

    // gmem load indexing: 1024 float4 per operand tile; 4 per thread
    const int ldrow0 = tid >> 3;          // consecutive 8 threads share a row slice
    const int ldkc   = (tid & 7) * 4;

    for (int k0 = 0; k0 < K; k0 += 32) {
        // ---- load gmem -> regs ----
        float4 a4[4], w4[4];
        #pragma unroll
        for (int i = 0; i < 4; i++) {
            int row = ldrow0 + i * 32;
            a4[i] = *(const float4*)(A + (size_t)(brow + row) * K + k0 + ldkc);
            w4[i] = *(const float4*)(W + (size_t)(bcol + row) * K + k0 + ldkc);
        }
        __syncthreads();
        // ---- split+store to smem ----
        #pragma unroll
        for (int i = 0; i < 4; i++) {
            int row = ldrow0 + i * 32;
            const float av[4] = {a4[i].x, a4[i].y, a4[i].z, a4[i].w};
            const float wv[4] = {w4[i].x, w4[i].y, w4[i].z, w4[i].w};
            #pragma unroll
            for (int j = 0; j < 4; j++) {
                __nv_bfloat16 h = __float2bfloat16_rn(av[j]);
                sAhi[row][ldkc + j] = h;
                sAlo[row][ldkc + j] = __float2bfloat16_rn(av[j] - __bfloat162float(h));
                __nv_bfloat16 g = __float2bfloat16_rn(wv[j]);
                sWhi[row][ldkc + j] = g;
                sWlo[row][ldkc + j] = __float2bfloat16_rn(wv[j] - __bfloat162float(g));
            }
        }
        __syncthreads();

        // ---- compute: two k16 steps ----
        #pragma unroll
        for (int ks = 0; ks < 2; ks++) {
            const uint32_t kadd = (uint32_t)(ks * 16 * 2);
            uint32_t ahi[4][4], alo[4][4], bhi[2][4], blo[2][4];
            #pragma unroll
            for (int mi = 0; mi < 4; mi++) {
                ldm4(ahi[mi], bAhi + offA[mi] + kadd);
                ldm4(alo[mi], bAlo + offA[mi] + kadd);
            }
            #pragma unroll
            for (int ni2 = 0; ni2 < 2; ni2++) {
                ldm4(bhi[ni2], bWhi + offB[ni2] + kadd);
                ldm4(blo[ni2], bWlo + offB[ni2] + kadd);
            }
            #pragma unroll
            for (int mi = 0; mi < 4; mi++) {
                #pragma unroll
                for (int nf = 0; nf < 4; nf++) {
                    const int ni2 = nf >> 1;
                    const int s   = (nf & 1) * 2;
                    uint32_t bh[2] = { bhi[ni2][s], bhi[ni2][s + 1] };
                    uint32_t bl[2] = { blo[ni2][s], blo[ni2][s + 1] };
                    mma16816(acc[mi][nf], ahi[mi], bh);
                    mma16816(acc[mi][nf], alo[mi], bh);
                    mma16816(acc[mi][nf], ahi[mi], bl);
                }
            }
        }
    }

    // ---- epilogue ----
    const int gid = lane >> 2;
    const int tig = lane & 3;
    #pragma unroll
    for (int mi = 0; mi < 4; mi++) {
        #pragma unroll
        for (int nf = 0; nf < 4; nf++) {
            int row = brow + wm * 64 + mi * 16 + gid;
            int col = bcol + wn * 32 + nf * 8 + tig * 2;
            *(float2*)(C + (size_t)row * N + col) =
                make_float2(acc[mi][nf][0], acc[mi][nf][1]);
            *(float2*)(C + (size_t)(row + 8) * N + col) =
                make_float2(acc[mi][nf][2], acc[mi][nf][3]);
        }
    }
}

// =====================================================================
// Depthwise causal conv (width 4) + bias + SiLU
// =====================================================================
__global__ void conv_silu_kernel(const float* __restrict__ xz,
                                 const float* __restrict__ cw,
                                 const float* __restrict__ cb,
                                 float* __restrict__ xconv)
{
    int idx = blockIdx.x * blockDim.x + threadIdx.x;
    if (idx >= MROWS * DD) return;
    int d  = idx & (DD - 1);
    int bt = idx >> 10;
    int t  = bt & (TT - 1);
    int b  = bt >> 11;

    float acc = cb[d];
    #pragma unroll
    for (int j = 0; j < DCONV; j++) {
        int tt = t - (DCONV - 1) + j;
        if (tt >= 0)
            acc = fmaf(xz[(size_t)(b * TT + tt) * E2 + d], cw[d * DCONV + j], acc);
    }
    float s = acc / (1.0f + __expf(-acc));
    xconv[(size_t)bt * DD + d] = s;
}

// =====================================================================
// x_proj: params[row, e] = sum_k xconv[row,k] * W[e,k]  (33 outputs/row)
// =====================================================================
__global__ __launch_bounds__(64) void xproj_kernel(const float* __restrict__ xconv,
                                                   const float* __restrict__ W,
                                                   float* __restrict__ params)
{
    __shared__ float sx[DD];
    int row = blockIdx.x;
    const float4* xr = (const float4*)(xconv + (size_t)row * DD);
    for (int i = threadIdx.x; i < DD / 4; i += 64)
        ((float4*)sx)[i] = xr[i];
    __syncthreads();

    int e = threadIdx.x;
    if (e < NPAR) {
        const float* w = W + (size_t)e * DD;
        float acc0 = 0.f, acc1 = 0.f, acc2 = 0.f, acc3 = 0.f;
        #pragma unroll 4
        for (int k = 0; k < DD; k += 4) {
            float4 w4 = *(const float4*)(w + k);
            acc0 = fmaf(sx[k + 0], w4.x, acc0);
            acc1 = fmaf(sx[k + 1], w4.y, acc1);
            acc2 = fmaf(sx[k + 2], w4.z, acc2);
            acc3 = fmaf(sx[k + 3], w4.w, acc3);
        }
        params[(size_t)row * NPAR + e] = (acc0 + acc1) + (acc2 + acc3);
    }
}

// =====================================================================
// Selective scan with manual next-row prefetch (software pipelining)
// =====================================================================
__global__ __launch_bounds__(32) void scan_kernel(const float* __restrict__ params,
                                                  const float* __restrict__ xconv,
                                                  const float* __restrict__ xz,
                                                  const float* __restrict__ dtw,
                                                  const float* __restrict__ dtb,
                                                  const float* __restrict__ A_log,
                                                  float* __restrict__ y)
{
    const int b = blockIdx.x / (DD / 32);
    const int d = (blockIdx.x % (DD / 32)) * 32 + threadIdx.x;

    float a[NN];
    #pragma unroll
    for (int n = 0; n < NN; n++)
        a[n] = -expf(A_log[(size_t)d * NN + n]);

    const float w    = dtw[d];
    const float bias = dtb[d];

    float h[NN];
    #pragma unroll
    for (int n = 0; n < NN; n++) h[n] = 0.f;

    const size_t rowbase = (size_t)b * TT;

    // prefetch t=0
    float pB[NN], pC[NN], sraw, xv, zv;
    {
        const float* p = params + rowbase * NPAR;
        #pragma unroll
        for (int n = 0; n < NN; n++) { pB[n] = p[n]; pC[n] = p[NN + n]; }
        sraw = p[32];
        xv = xconv[rowbase * DD + d];
        zv = xz[rowbase * E2 + DD + d];
    }

    for (int t = 0; t < TT; t++) {
        const size_t r = rowbase + t;
        // current values
        float cB[NN], cC[NN];
        #pragma unroll
        for (int n = 0; n < NN; n++) { cB[n] = pB[n]; cC[n] = pC[n]; }
        float cs = sraw, cx = xv, cz = zv;

        // prefetch next row early (independent of recurrence chain)
        if (t + 1 < TT) {
            const float* p = params + (r + 1) * NPAR;
            #pragma unroll
            for (int n = 0; n < NN; n++) { pB[n] = p[n]; pC[n] = p[NN + n]; }
            sraw = p[32];
            xv = xconv[(r + 1) * DD + d];
            zv = xz[(r + 1) * E2 + DD + d];
        }

        float v  = fmaf(cs, w, bias);
        float dt = (v > 20.f) ? v : log1pf(__expf(v));
        float dtx = dt * cx;
        float yv = 0.f;
        #pragma unroll
        for (int n = 0; n < NN; n++) {
            float dA = __expf(dt * a[n]);
            h[n] = fmaf(dA, h[n], dtx * cB[n]);
            yv = fmaf(h[n], cC[n], yv);
        }
        float sil = cz / (1.0f + __expf(-cz));
        y[r * DD + d] = yv * sil;
    }
}

// =====================================================================
// launch
// =====================================================================
extern "C" void kernel_launch(void* const* d_in, const int* in_sizes, int n_in,
                              void* d_out, int out_size)
{
    const float* x         = (const float*)d_in[0];
    const float* in_proj_w = (const float*)d_in[1];
    const float* conv_w    = (const float*)d_in[2];
    const float* conv_b    = (const float*)d_in[3];
    const float* x_proj_w  = (const float*)d_in[4];
    const float* dt_proj_w = (const float*)d_in[5];
    const float* dt_proj_b = (const float*)d_in[6];
    const float* A_log     = (const float*)d_in[7];
    const float* out_proj_w= (const float*)d_in[8];
    float* out = (float*)d_out;

    float *xz, *xconv, *params, *yb;
    cudaGetSymbolAddress((void**)&xz,     g_xz);
    cudaGetSymbolAddress((void**)&xconv,  g_xconv);
    cudaGetSymbolAddress((void**)&params, g_params);
    cudaGetSymbolAddress((void**)&yb,     g_y);

    // 1) in_proj: (4096,1024) @ (2048,1024)^T -> (4096,2048)  [tensor cores]
    {
        dim3 grid(E2 / 128, MROWS / 128);
        gemm_tc_split<<<grid, 256>>>(x, in_proj_w, xz, MROWS, E2, DD);
    }
    // 2) depthwise conv + SiLU
    {
        int total = MROWS * DD;
        conv_silu_kernel<<<(total + 255) / 256, 256>>>(xz, conv_w, conv_b, xconv);
    }
    // 3) x_proj: (4096,1024) @ (33,1024)^T -> (4096,33)
    xproj_kernel<<<MROWS, 64>>>(xconv, x_proj_w, params);
    // 4) selective scan (+ gate by silu(z))
    scan_kernel<<<BB * (DD / 32), 32>>>(params, xconv, xz, dt_proj_w, dt_proj_b, A_log, yb);
    // 5) out_proj: (4096,1024) @ (1024,1024)^T -> (4096,1024)  [tensor cores]
    {
        dim3 grid(DD / 128, MROWS / 128);
        gemm_tc_split<<<grid, 256>>>(yb, out_proj_w, out, MROWS, DD, DD);
    }
}

// round 3
// speedup vs baseline: 5.1043x; 2.5474x over previous
#include <cuda_runtime.h>
#include <cuda_bf16.h>
#include <cstdint>

// Problem dims (fixed by the reference)
#define BB 2
#define TT 2048
#define DD 1024
#define NN 16
#define DCONV 4
#define MROWS (BB*TT)          // 4096
#define E2 (2*DD)              // 2048
#define NPAR (2*NN+1)          // 33
#define NCH 32                 // scan chunks
#define CHL (TT/NCH)           // 64 steps per chunk

// ---------- scratch (static device allocations only) ----------
__device__ float g_xz[(size_t)MROWS * E2];        // in_proj output (x_in | z)
__device__ float g_xconv[(size_t)MROWS * DD];     // conv+silu output
__device__ float g_params[(size_t)MROWS * NPAR];  // x_proj output (B,C,dt_raw)
__device__ __nv_bfloat16 g_xhi[(size_t)MROWS * DD], g_xlo[(size_t)MROWS * DD];
__device__ __nv_bfloat16 g_w1hi[(size_t)E2 * DD],  g_w1lo[(size_t)E2 * DD];
__device__ __nv_bfloat16 g_w2hi[(size_t)DD * DD],  g_w2lo[(size_t)DD * DD];
__device__ __nv_bfloat16 g_yhi[(size_t)MROWS * DD], g_ylo[(size_t)MROWS * DD];
__device__ float g_P   [(size_t)BB * NCH * NN * DD];
__device__ float g_hend[(size_t)BB * NCH * NN * DD];
__device__ float g_hini[(size_t)BB * NCH * NN * DD];

// =====================================================================
// fp32 -> bf16 hi/lo split (vectorized)
// =====================================================================
__global__ void split_kernel(const float* __restrict__ in,
                             __nv_bfloat16* __restrict__ hi,
                             __nv_bfloat16* __restrict__ lo, int n4)
{
    int i = blockIdx.x * blockDim.x + threadIdx.x;
    if (i >= n4) return;
    float4 v = ((const float4*)in)[i];
    __nv_bfloat16 hx = __float2bfloat16_rn(v.x);
    __nv_bfloat16 hy = __float2bfloat16_rn(v.y);
    __nv_bfloat16 hz = __float2bfloat16_rn(v.z);
    __nv_bfloat16 hw = __float2bfloat16_rn(v.w);
    __nv_bfloat162 h01; h01.x = hx; h01.y = hy;
    __nv_bfloat162 h23; h23.x = hz; h23.y = hw;
    ((__nv_bfloat162*)hi)[i*2]   = h01;
    ((__nv_bfloat162*)hi)[i*2+1] = h23;
    __nv_bfloat162 l01, l23;
    l01.x = __float2bfloat16_rn(v.x - __bfloat162float(hx));
    l01.y = __float2bfloat16_rn(v.y - __bfloat162float(hy));
    l23.x = __float2bfloat16_rn(v.z - __bfloat162float(hz));
    l23.y = __float2bfloat16_rn(v.w - __bfloat162float(hw));
    ((__nv_bfloat162*)lo)[i*2]   = l01;
    ((__nv_bfloat162*)lo)[i*2+1] = l23;
}

// =====================================================================
// Tensor-core GEMM, pre-split bf16 hi/lo, cp.async double-buffered.
//   C[M,N] = (Ahi+Alo)[M,K] @ (Whi+Wlo)[N,K]^T  (3-term)
// Block 128x128, BK=32, 256 threads, warp tile 64x32.
// =====================================================================
#define GLDA 40                      // bf16 elems per smem row (32 + 8 pad)
#define SM_ARR (128*GLDA)            // elems per operand array
#define SM_STAGE (4*SM_ARR)          // elems per stage (Ahi,Alo,Whi,Wlo)
#define GEMM_SMEM (2*SM_STAGE*2)     // bytes (2 stages, bf16)

__device__ __forceinline__ void mma16816(float* c, const uint32_t* a, const uint32_t* b) {
    asm volatile(
        "mma.sync.aligned.m16n8k16.row.col.f32.bf16.bf16.f32 "
        "{%0,%1,%2,%3}, {%4,%5,%6,%7}, {%8,%9}, {%0,%1,%2,%3};"
        : "+f"(c[0]), "+f"(c[1]), "+f"(c[2]), "+f"(c[3])
        : "r"(a[0]), "r"(a[1]), "r"(a[2]), "r"(a[3]), "r"(b[0]), "r"(b[1]));
}
__device__ __forceinline__ void ldm4(uint32_t* r, uint32_t addr) {
    asm volatile(
        "ldmatrix.sync.aligned.m8n8.x4.shared.b16 {%0,%1,%2,%3}, [%4];"
        : "=r"(r[0]), "=r"(r[1]), "=r"(r[2]), "=r"(r[3]) : "r"(addr));
}
__device__ __forceinline__ void cpasync16(uint32_t dst, const void* src) {
    asm volatile("cp.async.cg.shared.global [%0], [%1], 16;" :: "r"(dst), "l"(src));
}

__global__ __launch_bounds__(256) void gemm_tc_bf16(
    const __nv_bfloat16* __restrict__ Ahi, const __nv_bfloat16* __restrict__ Alo,
    const __nv_bfloat16* __restrict__ Whi, const __nv_bfloat16* __restrict__ Wlo,
    float* __restrict__ C, int M, int N, int K)
{
    extern __shared__ __align__(16) __nv_bfloat16 dsm[];

    const int tid  = threadIdx.x;
    const int lane = tid & 31;
    const int warp = tid >> 5;
    const int wm   = warp >> 2;
    const int wn   = warp & 3;
    const int brow = blockIdx.y * 128;
    const int bcol = blockIdx.x * 128;

    float acc[4][4][4];
    #pragma unroll
    for (int i = 0; i < 4; i++)
        #pragma unroll
        for (int j = 0; j < 4; j++)
            #pragma unroll
            for (int k = 0; k < 4; k++) acc[i][j][k] = 0.f;

    const uint32_t sbase = (uint32_t)__cvta_generic_to_shared(dsm);

    // cp.async mapping: per array 512 x 16B chunks (128 rows x 4); 2 per thread.
    const int ldrow = tid >> 1;
    const int ldkc0 = (tid & 1) * 2;     // chunk 0..3 (16B = 8 bf16 each)
    const __nv_bfloat16* gA[4];
    gA[0] = Ahi + (size_t)(brow + ldrow) * K;
    gA[1] = Alo + (size_t)(brow + ldrow) * K;
    gA[2] = Whi + (size_t)(bcol + ldrow) * K;
    gA[3] = Wlo + (size_t)(bcol + ldrow) * K;

    // ldmatrix fragment offsets (bytes within one array)
    uint32_t offA[4];
    #pragma unroll
    for (int mi = 0; mi < 4; mi++) {
        int row = wm * 64 + mi * 16 + (lane & 15);
        int ko  = (lane >> 4) * 8;
        offA[mi] = (uint32_t)(row * GLDA + ko) * 2u;
    }
    uint32_t offB[2];
    #pragma unroll
    for (int ni2 = 0; ni2 < 2; ni2++) {
        int row = wn * 32 + ni2 * 16 + (lane & 7) + ((lane >> 4) << 3);
        int ko  = ((lane >> 3) & 1) * 8;
        offB[ni2] = (uint32_t)(row * GLDA + ko) * 2u;
    }

    const int NK = K / 32;

    // issue stage 0
    {
        #pragma unroll
        for (int arr = 0; arr < 4; arr++)
            #pragma unroll
            for (int c = 0; c < 2; c++) {
                int kc = ldkc0 + c;
                uint32_t dst = sbase + (uint32_t)(arr * SM_ARR + ldrow * GLDA) * 2u + kc * 16;
                cpasync16(dst, gA[arr] + kc * 8);
            }
        asm volatile("cp.async.commit_group;");
    }

    for (int kt = 0; kt < NK; kt++) {
        const int cur = kt & 1;
        if (kt + 1 < NK) {
            const int nxt = (kt + 1) & 1;
            const int k0n = (kt + 1) * 32;
            #pragma unroll
            for (int arr = 0; arr < 4; arr++)
                #pragma unroll
                for (int c = 0; c < 2; c++) {
                    int kc = ldkc0 + c;
                    uint32_t dst = sbase + (uint32_t)(nxt * SM_STAGE + arr * SM_ARR + ldrow * GLDA) * 2u + kc * 16;
                    cpasync16(dst, gA[arr] + k0n + kc * 8);
                }
            asm volatile("cp.async.commit_group;");
            asm volatile("cp.async.wait_group 1;");
        } else {
            asm volatile("cp.async.wait_group 0;");
        }
        __syncthreads();

        const uint32_t stAhi = sbase + (uint32_t)(cur * SM_STAGE + 0 * SM_ARR) * 2u;
        const uint32_t stAlo = sbase + (uint32_t)(cur * SM_STAGE + 1 * SM_ARR) * 2u;
        const uint32_t stWhi = sbase + (uint32_t)(cur * SM_STAGE + 2 * SM_ARR) * 2u;
        const uint32_t stWlo = sbase + (uint32_t)(cur * SM_STAGE + 3 * SM_ARR) * 2u;

        #pragma unroll
        for (int ks = 0; ks < 2; ks++) {
            const uint32_t kadd = (uint32_t)(ks * 32);   // 16 bf16 = 32 bytes
            uint32_t ahi[4][4], alo[4][4], bhi[2][4], blo[2][4];
            #pragma unroll
            for (int mi = 0; mi < 4; mi++) {
                ldm4(ahi[mi], stAhi + offA[mi] + kadd);
                ldm4(alo[mi], stAlo + offA[mi] + kadd);
            }
            #pragma unroll
            for (int ni2 = 0; ni2 < 2; ni2++) {
                ldm4(bhi[ni2], stWhi + offB[ni2] + kadd);
                ldm4(blo[ni2], stWlo + offB[ni2] + kadd);
            }
            #pragma unroll
            for (int mi = 0; mi < 4; mi++) {
                #pragma unroll
                for (int nf = 0; nf < 4; nf++) {
                    const int ni2 = nf >> 1;
                    const int s   = (nf & 1) * 2;
                    uint32_t bh[2] = { bhi[ni2][s], bhi[ni2][s + 1] };
                    uint32_t bl[2] = { blo[ni2][s], blo[ni2][s + 1] };
                    mma16816(acc[mi][nf], ahi[mi], bh);
                    mma16816(acc[mi][nf], alo[mi], bh);
                    mma16816(acc[mi][nf], ahi[mi], bl);
                }
            }
        }
        __syncthreads();
    }

    const int gid = lane >> 2;
    const int tig = lane & 3;
    #pragma unroll
    for (int mi = 0; mi < 4; mi++) {
        #pragma unroll
        for (int nf = 0; nf < 4; nf++) {
            int row = brow + wm * 64 + mi * 16 + gid;
            int col = bcol + wn * 32 + nf * 8 + tig * 2;
            *(float2*)(C + (size_t)row * N + col) =
                make_float2(acc[mi][nf][0], acc[mi][nf][1]);
            *(float2*)(C + (size_t)(row + 8) * N + col) =
                make_float2(acc[mi][nf][2], acc[mi][nf][3]);
        }
    }
}

// =====================================================================
// Depthwise causal conv (width 4) + bias + SiLU
// =====================================================================
__global__ void conv_silu_kernel(const float* __restrict__ xz,
                                 const float* __restrict__ cw,
                                 const float* __restrict__ cb,
                                 float* __restrict__ xconv)
{
    int idx = blockIdx.x * blockDim.x + threadIdx.x;
    if (idx >= MROWS * DD) return;
    int d  = idx & (DD - 1);
    int bt = idx >> 10;
    int t  = bt & (TT - 1);
    int b  = bt >> 11;

    float acc = cb[d];
    #pragma unroll
    for (int j = 0; j < DCONV; j++) {
        int tt = t - (DCONV - 1) + j;
        if (tt >= 0)
            acc = fmaf(xz[(size_t)(b * TT + tt) * E2 + d], cw[d * DCONV + j], acc);
    }
    float s = acc / (1.0f + __expf(-acc));
    xconv[(size_t)bt * DD + d] = s;
}

// =====================================================================
// Tiled x_proj: block = (33,8) threads, 32 rows per block.
// params[row, e] = sum_k xconv[row,k] * W[e,k]
// =====================================================================
__global__ void xproj_tiled(const float* __restrict__ xconv,
                            const float* __restrict__ W,
                            float* __restrict__ params)
{
    __shared__ float sx[32][68];
    const int e  = threadIdx.x;   // 0..32
    const int rg = threadIdx.y;   // 0..7
    const int flat = rg * 33 + e;
    const int row0 = blockIdx.x * 32;

    float acc[4] = {0.f, 0.f, 0.f, 0.f};

    for (int k0 = 0; k0 < DD; k0 += 64) {
        __syncthreads();
        // load 32 rows x 64 floats = 512 float4
        for (int c = flat; c < 512; c += 264) {
            int ri = c >> 4;
            int k4 = c & 15;
            float4 v = *(const float4*)(xconv + (size_t)(row0 + ri) * DD + k0 + k4 * 4);
            *(float4*)&sx[ri][k4 * 4] = v;
        }
        __syncthreads();
        const float* wrow = W + (size_t)e * DD + k0;
        #pragma unroll
        for (int k4 = 0; k4 < 16; k4++) {
            float4 w4 = *(const float4*)(wrow + k4 * 4);
            #pragma unroll
            for (int j = 0; j < 4; j++) {
                const float* sxr = sx[rg * 4 + j];
                acc[j] = fmaf(sxr[k4*4+0], w4.x, acc[j]);
                acc[j] = fmaf(sxr[k4*4+1], w4.y, acc[j]);
                acc[j] = fmaf(sxr[k4*4+2], w4.z, acc[j]);
                acc[j] = fmaf(sxr[k4*4+3], w4.w, acc[j]);
            }
        }
    }
    #pragma unroll
    for (int j = 0; j < 4; j++)
        params[(size_t)(row0 + rg * 4 + j) * NPAR + e] = acc[j];
}

// =====================================================================
// Chunked scan, pass A: local scan from h=0; store decay product P and h_end.
// grid: BB*NCH*(DD/32) blocks of 32
// =====================================================================
__global__ __launch_bounds__(32) void scanA_kernel(const float* __restrict__ params,
                                                   const float* __restrict__ xconv,
                                                   const float* __restrict__ dtw,
                                                   const float* __restrict__ dtb,
                                                   const float* __restrict__ A_log,
                                                   float* __restrict__ Pout,
                                                   float* __restrict__ hend)
{
    const int dg = blockIdx.x & 31;
    const int c  = (blockIdx.x >> 5) & (NCH - 1);
    const int b  = blockIdx.x >> 10;
    const int d  = dg * 32 + threadIdx.x;

    float a[NN];
    #pragma unroll
    for (int n = 0; n < NN; n++)
        a[n] = -expf(A_log[(size_t)d * NN + n]);
    const float w    = dtw[d];
    const float bias = dtb[d];

    float h[NN], P[NN];
    #pragma unroll
    for (int n = 0; n < NN; n++) { h[n] = 0.f; P[n] = 1.f; }

    const size_t rowbase = (size_t)b * TT + (size_t)c * CHL;
    for (int t = 0; t < CHL; t++) {
        const size_t r = rowbase + t;
        const float* p = params + r * NPAR;
        float v  = fmaf(p[32], w, bias);
        float dt = (v > 20.f) ? v : __logf(1.0f + __expf(v));
        float dtx = dt * xconv[r * DD + d];
        #pragma unroll
        for (int n = 0; n < NN; n++) {
            float e = __expf(dt * a[n]);
            h[n] = fmaf(e, h[n], dtx * p[n]);
            P[n] *= e;
        }
    }
    const size_t o = ((size_t)(b * NCH + c) * NN) * DD + d;
    #pragma unroll
    for (int n = 0; n < NN; n++) {
        hend[o + (size_t)n * DD] = h[n];
        Pout[o + (size_t)n * DD] = P[n];
    }
}

// =====================================================================
// Pass B: sequential chunk combine. thread per (b,d).
// =====================================================================
__global__ void scanB_kernel(const float* __restrict__ P,
                             const float* __restrict__ hend,
                             float* __restrict__ hini)
{
    int gid = blockIdx.x * blockDim.x + threadIdx.x;
    if (gid >= BB * DD) return;
    int d = gid & (DD - 1);
    int b = gid >> 10;

    float h[NN];
    #pragma unroll
    for (int n = 0; n < NN; n++) h[n] = 0.f;

    for (int c = 0; c < NCH; c++) {
        const size_t o = ((size_t)(b * NCH + c) * NN) * DD + d;
        #pragma unroll
        for (int n = 0; n < NN; n++) {
            hini[o + (size_t)n * DD] = h[n];
            h[n] = fmaf(P[o + (size_t)n * DD], h[n], hend[o + (size_t)n * DD]);
        }
    }
}

// =====================================================================
// Pass C: re-run chunks from correct h_init; emit y = (h·C)*silu(z),
// written directly as bf16 hi/lo for the out_proj GEMM.
// =====================================================================
__global__ __launch_bounds__(32) void scanC_kernel(const float* __restrict__ params,
                                                   const float* __restrict__ xconv,
                                                   const float* __restrict__ xz,
                                                   const float* __restrict__ dtw,
                                                   const float* __restrict__ dtb,
                                                   const float* __restrict__ A_log,
                                                   const float* __restrict__ hini,
                                                   __nv_bfloat16* __restrict__ yhi,
                                                   __nv_bfloat16* __restrict__ ylo)
{
    const int dg = blockIdx.x & 31;
    const int c  = (blockIdx.x >> 5) & (NCH - 1);
    const int b  = blockIdx.x >> 10;
    const int d  = dg * 32 + threadIdx.x;

    float a[NN];
    #pragma unroll
    for (int n = 0; n < NN; n++)
        a[n] = -expf(A_log[(size_t)d * NN + n]);
    const float w    = dtw[d];
    const float bias = dtb[d];

    float h[NN];
    const size_t o = ((size_t)(b * NCH + c) * NN) * DD + d;
    #pragma unroll
    for (int n = 0; n < NN; n++) h[n] = hini[o + (size_t)n * DD];

    const size_t rowbase = (size_t)b * TT + (size_t)c * CHL;
    for (int t = 0; t < CHL; t++) {
        const size_t r = rowbase + t;
        const float* p = params + r * NPAR;
        float v  = fmaf(p[32], w, bias);
        float dt = (v > 20.f) ? v : __logf(1.0f + __expf(v));
        float dtx = dt * xconv[r * DD + d];
        float zv  = xz[r * E2 + DD + d];
        float yv = 0.f;
        #pragma unroll
        for (int n = 0; n < NN; n++) {
            float e = __expf(dt * a[n]);
            h[n] = fmaf(e, h[n], dtx * p[n]);
            yv = fmaf(h[n], p[NN + n], yv);
        }
        float sil = zv / (1.0f + __expf(-zv));
        float val = yv * sil;
        __nv_bfloat16 hh = __float2bfloat16_rn(val);
        yhi[r * DD + d] = hh;
        ylo[r * DD + d] = __float2bfloat16_rn(val - __bfloat162float(hh));
    }
}

// =====================================================================
// launch
// =====================================================================
extern "C" void kernel_launch(void* const* d_in, const int* in_sizes, int n_in,
                              void* d_out, int out_size)
{
    const float* x         = (const float*)d_in[0];
    const float* in_proj_w = (const float*)d_in[1];
    const float* conv_w    = (const float*)d_in[2];
    const float* conv_b    = (const float*)d_in[3];
    const float* x_proj_w  = (const float*)d_in[4];
    const float* dt_proj_w = (const float*)d_in[5];
    const float* dt_proj_b = (const float*)d_in[6];
    const float* A_log     = (const float*)d_in[7];
    const float* out_proj_w= (const float*)d_in[8];
    float* out = (float*)d_out;

    float *xz, *xconv, *params, *P, *hend, *hini;
    __nv_bfloat16 *xhi, *xlo, *w1hi, *w1lo, *w2hi, *w2lo, *yhi, *ylo;
    cudaGetSymbolAddress((void**)&xz,     g_xz);
    cudaGetSymbolAddress((void**)&xconv,  g_xconv);
    cudaGetSymbolAddress((void**)&params, g_params);
    cudaGetSymbolAddress((void**)&P,      g_P);
    cudaGetSymbolAddress((void**)&hend,   g_hend);
    cudaGetSymbolAddress((void**)&hini,   g_hini);
    cudaGetSymbolAddress((void**)&xhi,    g_xhi);
    cudaGetSymbolAddress((void**)&xlo,    g_xlo);
    cudaGetSymbolAddress((void**)&w1hi,   g_w1hi);
    cudaGetSymbolAddress((void**)&w1lo,   g_w1lo);
    cudaGetSymbolAddress((void**)&w2hi,   g_w2hi);
    cudaGetSymbolAddress((void**)&w2lo,   g_w2lo);
    cudaGetSymbolAddress((void**)&yhi,    g_yhi);
    cudaGetSymbolAddress((void**)&ylo,    g_ylo);

    cudaFuncSetAttribute(gemm_tc_bf16,
                         cudaFuncAttributeMaxDynamicSharedMemorySize, GEMM_SMEM);

    // 0) pre-split fp32 -> bf16 hi/lo
    split_kernel<<<(MROWS*DD/4 + 255)/256, 256>>>(x, xhi, xlo, MROWS*DD/4);
    split_kernel<<<(E2*DD/4    + 255)/256, 256>>>(in_proj_w, w1hi, w1lo, E2*DD/4);
    split_kernel<<<(DD*DD/4    + 255)/256, 256>>>(out_proj_w, w2hi, w2lo, DD*DD/4);

    // 1) in_proj: (4096,1024) @ (2048,1024)^T -> (4096,2048)
    {
        dim3 grid(E2 / 128, MROWS / 128);
        gemm_tc_bf16<<<grid, 256, GEMM_SMEM>>>(xhi, xlo, w1hi, w1lo, xz, MROWS, E2, DD);
    }
    // 2) depthwise conv + SiLU
    conv_silu_kernel<<<(MROWS*DD + 255)/256, 256>>>(xz, conv_w, conv_b, xconv);
    // 3) x_proj (tiled)
    {
        dim3 blk(33, 8);
        xproj_tiled<<<MROWS / 32, blk>>>(xconv, x_proj_w, params);
    }
    // 4) chunked selective scan
    scanA_kernel<<<BB * NCH * (DD/32), 32>>>(params, xconv, dt_proj_w, dt_proj_b, A_log, P, hend);
    scanB_kernel<<<(BB*DD + 255)/256, 256>>>(P, hend, hini);
    scanC_kernel<<<BB * NCH * (DD/32), 32>>>(params, xconv, xz, dt_proj_w, dt_proj_b, A_log, hini, yhi, ylo);
    // 5) out_proj: (4096,1024) @ (1024,1024)^T -> (4096,1024)
    {
        dim3 grid(DD / 128, MROWS / 128);
        gemm_tc_bf16<<<grid, 256, GEMM_SMEM>>>(yhi, ylo, w2hi, w2lo, out, MROWS, DD, DD);
    }
}